// round 3
// baseline (speedup 1.0000x reference)
#include <cuda_runtime.h>
#include <cuda_bf16.h>

// Inputs (metadata order):
//   d_in[0] : energy_readout            float32 [262144]
//   d_in[1] : atomic_numbers            int32   [8388608]
//   d_in[2] : atomic_subsystem_indices  int32   [8388608]  (sorted ascending)
//   d_in[3] : self_energies_tensor      float32 [100]
// Output: float32 [262144] = energy_readout + segment_sum(se[Z], seg_idx)

#define LUT_SIZE_MAX 128
#define CHUNK 16          // atoms per thread
#define TPB 256

__global__ void init_out_kernel(const float* __restrict__ e,
                                float* __restrict__ out, int n) {
    int i = blockIdx.x * blockDim.x + threadIdx.x;
    if (i < n) out[i] = e[i];
}

__global__ void __launch_bounds__(TPB)
self_energy_segsum_kernel(const int* __restrict__ zs,
                          const int* __restrict__ seg,
                          const float* __restrict__ se,
                          float* __restrict__ out,
                          int n_atoms, int n_se) {
    // Bank-replicated LUT: copy c of entry z lives at rep[z*32 + c].
    // Lane l always reads rep[z*32 + l] -> bank l -> conflict-free gather.
    __shared__ float s_rep[LUT_SIZE_MAX * 32];

    {
        // Fill all 32 replicas. Each thread writes words strided by TPB.
        for (int i = threadIdx.x; i < LUT_SIZE_MAX * 32; i += TPB) {
            int z = i >> 5;
            s_rep[i] = (z < n_se) ? __ldg(se + z) : 0.0f;
        }
    }
    __syncthreads();

    const int lane = threadIdx.x & 31;
    // Per-lane base so that (z<<5) + lane hits bank == lane always.
    const float* lut = s_rep + lane;

    long long base = (long long)(blockIdx.x * blockDim.x + threadIdx.x) * CHUNK;
    if (base >= n_atoms) return;

    int cur_seg = -1;
    float run_sum = 0.0f;

    if (base + CHUNK <= n_atoms) {
        const int4* z4 = reinterpret_cast<const int4*>(zs + base);
        const int4* s4 = reinterpret_cast<const int4*>(seg + base);

        int4 zv[CHUNK / 4];
        int4 sv[CHUNK / 4];
#pragma unroll
        for (int v = 0; v < CHUNK / 4; v++) {  // front-batched: MLP=8
            zv[v] = __ldcs(z4 + v);            // streaming: read-once data
            sv[v] = __ldcs(s4 + v);
        }

#pragma unroll
        for (int v = 0; v < CHUNK / 4; v++) {
            int z[4] = {zv[v].x, zv[v].y, zv[v].z, zv[v].w};
            int s[4] = {sv[v].x, sv[v].y, sv[v].z, sv[v].w};
#pragma unroll
            for (int k = 0; k < 4; k++) {
                if (s[k] != cur_seg) {
                    if (cur_seg >= 0) atomicAdd(out + cur_seg, run_sum);
                    cur_seg = s[k];
                    run_sum = 0.0f;
                }
                run_sum += lut[z[k] << 5];
            }
        }
    } else {
        // Tail safety (not expected with 8388608 atoms, but be general)
        long long end = n_atoms;
        for (long long i = base; i < end; i++) {
            int s = seg[i];
            if (s != cur_seg) {
                if (cur_seg >= 0) atomicAdd(out + cur_seg, run_sum);
                cur_seg = s;
                run_sum = 0.0f;
            }
            run_sum += lut[zs[i] << 5];
        }
    }

    if (cur_seg >= 0) atomicAdd(out + cur_seg, run_sum);
}

extern "C" void kernel_launch(void* const* d_in, const int* in_sizes, int n_in,
                              void* d_out, int out_size) {
    const float* energy = (const float*)d_in[0];
    const int*   zs     = (const int*)d_in[1];
    const int*   seg    = (const int*)d_in[2];
    const float* se     = (const float*)d_in[3];
    float* out = (float*)d_out;

    int n_mol   = in_sizes[0];
    int n_atoms = in_sizes[1];
    int n_se    = in_sizes[3];

    // 1) out = energy_readout  (d_out comes in poisoned)
    {
        int blocks = (n_mol + TPB - 1) / TPB;
        init_out_kernel<<<blocks, TPB>>>(energy, out, n_mol);
    }

    // 2) segment-sum of gathered self energies via run-compressed atomics
    {
        long long threads_needed = ((long long)n_atoms + CHUNK - 1) / CHUNK;
        int blocks = (int)((threads_needed + TPB - 1) / TPB);
        self_energy_segsum_kernel<<<blocks, TPB>>>(zs, seg, se, out, n_atoms, n_se);
    }
}

// round 4
// speedup vs baseline: 1.5292x; 1.5292x over previous
#include <cuda_runtime.h>
#include <cuda_bf16.h>

// Inputs (metadata order):
//   d_in[0] : energy_readout            float32 [262144]
//   d_in[1] : atomic_numbers            int32   [8388608]
//   d_in[2] : atomic_subsystem_indices  int32   [8388608]  (sorted ascending)
//   d_in[3] : self_energies_tensor      float32 [100]
// Output: float32 [262144] = energy_readout + segment_sum(se[Z], seg_idx)

#define LUT_SIZE_MAX 128
#define CHUNK 8           // atoms per thread
#define TPB 256

__global__ void init_out_kernel(const float* __restrict__ e,
                                float* __restrict__ out, int n) {
    int i = blockIdx.x * blockDim.x + threadIdx.x;
    if (i < n) out[i] = e[i];
}

__global__ void __launch_bounds__(TPB, 8)
self_energy_segsum_kernel(const int* __restrict__ zs,
                          const int* __restrict__ seg,
                          const float* __restrict__ se,
                          float* __restrict__ out,
                          int n_atoms, int n_se) {
    __shared__ float s_se[LUT_SIZE_MAX];
    for (int i = threadIdx.x; i < LUT_SIZE_MAX; i += blockDim.x)
        s_se[i] = (i < n_se) ? se[i] : 0.0f;
    __syncthreads();

    long long base = (long long)(blockIdx.x * blockDim.x + threadIdx.x) * CHUNK;
    if (base >= n_atoms) return;

    int cur_seg = -1;
    float run_sum = 0.0f;

    if (base + CHUNK <= n_atoms) {
        // Fast path: vectorized int4 loads, all issued before any compute (MLP=4)
        const int4* z4 = reinterpret_cast<const int4*>(zs + base);
        const int4* s4 = reinterpret_cast<const int4*>(seg + base);

        int4 zv[CHUNK / 4];
        int4 sv[CHUNK / 4];
#pragma unroll
        for (int v = 0; v < CHUNK / 4; v++) {
            zv[v] = z4[v];
            sv[v] = s4[v];
        }

#pragma unroll
        for (int v = 0; v < CHUNK / 4; v++) {
            int z[4] = {zv[v].x, zv[v].y, zv[v].z, zv[v].w};
            int s[4] = {sv[v].x, sv[v].y, sv[v].z, sv[v].w};
#pragma unroll
            for (int k = 0; k < 4; k++) {
                if (s[k] != cur_seg) {
                    if (cur_seg >= 0) atomicAdd(out + cur_seg, run_sum);
                    cur_seg = s[k];
                    run_sum = 0.0f;
                }
                run_sum += s_se[z[k]];
            }
        }
    } else {
        // Tail safety (not expected with 8388608 atoms, but be general)
        long long end = n_atoms;
        for (long long i = base; i < end; i++) {
            int s = seg[i];
            if (s != cur_seg) {
                if (cur_seg >= 0) atomicAdd(out + cur_seg, run_sum);
                cur_seg = s;
                run_sum = 0.0f;
            }
            run_sum += s_se[zs[i]];
        }
    }

    if (cur_seg >= 0) atomicAdd(out + cur_seg, run_sum);
}

extern "C" void kernel_launch(void* const* d_in, const int* in_sizes, int n_in,
                              void* d_out, int out_size) {
    const float* energy = (const float*)d_in[0];
    const int*   zs     = (const int*)d_in[1];
    const int*   seg    = (const int*)d_in[2];
    const float* se     = (const float*)d_in[3];
    float* out = (float*)d_out;

    int n_mol   = in_sizes[0];
    int n_atoms = in_sizes[1];
    int n_se    = in_sizes[3];

    // 1) out = energy_readout  (d_out comes in poisoned)
    {
        int blocks = (n_mol + TPB - 1) / TPB;
        init_out_kernel<<<blocks, TPB>>>(energy, out, n_mol);
    }

    // 2) segment-sum of gathered self energies via run-compressed atomics
    {
        long long threads_needed = ((long long)n_atoms + CHUNK - 1) / CHUNK;
        int blocks = (int)((threads_needed + TPB - 1) / TPB);
        self_energy_segsum_kernel<<<blocks, TPB>>>(zs, seg, se, out, n_atoms, n_se);
    }
}